// round 14
// baseline (speedup 1.0000x reference)
#include <cuda_runtime.h>
#include <cuda_fp16.h>
#include <cstdint>

// Problem constants
#define BSZ   4
#define CSQ   1024
#define PSQ   1024
#define DIN   1024
#define NH    16
#define HDIM  64
#define TT    2048        // T = CS + PS
#define LQG   4096        // BSZ*CSQ global query rows
#define HD    1024        // NH*HDIM
#define SCALE 0.125f      // 1/sqrt(64)

// ---------------------------------------------------------------------------
// Scratch (device globals; no dynamic allocation allowed)
// ---------------------------------------------------------------------------
__device__ __half g_Ph [(size_t)NH * LQG * TT];          // 256 MB  pos scores (half)
__device__ __half h_qv [(size_t)LQG * HD];               //  8.4 MB half(q+v)
__device__ __half h_qu [(size_t)LQG * HD];               //  8.4 MB half(q+u)
__device__ __half h_kvh[(size_t)BSZ * TT * 2 * HD];      // 33.5 MB [k|v] half
__device__ __half h_ph [(size_t)TT * HD];                //  4.2 MB p half
__device__ __half h_aoh[(size_t)LQG * HD];               //  8.4 MB attn out half
// half inputs / transposed weights (one-time conversions)
__device__ __half h_in  [(size_t)BSZ * CSQ * DIN];
__device__ __half h_mem [(size_t)BSZ * PSQ * DIN];
__device__ __half h_pos [(size_t)TT * DIN];
__device__ __half h_Wkv_t [(size_t)(2 * HD) * DIN];      // [n][k]
__device__ __half h_Wq_t  [(size_t)HD * DIN];
__device__ __half h_Wp_t  [(size_t)HD * DIN];
__device__ __half h_Wout_t[(size_t)DIN * HD];

// ---------------------------------------------------------------------------
// Helpers
// ---------------------------------------------------------------------------
__device__ __forceinline__ void mma16(float* d, const uint32_t* a, const uint32_t* b) {
    asm volatile(
        "mma.sync.aligned.m16n8k16.row.col.f32.f16.f16.f32 "
        "{%0,%1,%2,%3}, {%4,%5,%6,%7}, {%8,%9}, {%0,%1,%2,%3};"
        : "+f"(d[0]), "+f"(d[1]), "+f"(d[2]), "+f"(d[3])
        : "r"(a[0]), "r"(a[1]), "r"(a[2]), "r"(a[3]), "r"(b[0]), "r"(b[1]));
}

__device__ __forceinline__ uint32_t smem_u32(const void* p) {
    return (uint32_t)__cvta_generic_to_shared(p);
}
#define CPA16(dst, src) \
    asm volatile("cp.async.cg.shared.global [%0], [%1], 16;" :: "r"(dst), "l"(src))
#define CPA_COMMIT() asm volatile("cp.async.commit_group;")
#define CPA_WAIT(n)  asm volatile("cp.async.wait_group %0;" :: "n"(n))
#define CPA_WAIT_TAIL(rem) do {                         \
        if ((rem) >= 2)      CPA_WAIT(2);               \
        else if ((rem) == 1) CPA_WAIT(1);               \
        else                 CPA_WAIT(0);               \
    } while (0)

// ---------------------------------------------------------------------------
// Conversion kernels (one-time)
// ---------------------------------------------------------------------------
__global__ void __launch_bounds__(256) cvt_f2h(const float* __restrict__ in,
                                               __half* __restrict__ out, int n4)
{
    int i = blockIdx.x * 256 + threadIdx.x;
    if (i < n4) {
        float4 v = ((const float4*)in)[i];
        __half2* o = (__half2*)out + (size_t)i * 2;
        o[0] = __floats2half2_rn(v.x, v.y);
        o[1] = __floats2half2_rn(v.z, v.w);
    }
}

// W [K][N] fp32 -> Wt [N][K] half (tiled transpose)
__global__ void __launch_bounds__(256) transpose_f2h(const float* __restrict__ in,
                                                     __half* __restrict__ out,
                                                     int K, int N)
{
    __shared__ __half tile[32][33];
    int k0 = blockIdx.y * 32, n0 = blockIdx.x * 32;
    int tx = threadIdx.x & 31, ty = threadIdx.x >> 5;   // 32 x 8
#pragma unroll
    for (int i = 0; i < 32; i += 8)
        tile[ty + i][tx] = __float2half(in[(size_t)(k0 + ty + i) * N + n0 + tx]);
    __syncthreads();
#pragma unroll
    for (int i = 0; i < 32; i += 8)
        out[(size_t)(n0 + ty + i) * K + k0 + tx] = tile[tx][ty + i];
}

// ---------------------------------------------------------------------------
// fp16 NT GEMM: A(MxK half) @ Bt(NxK half)^T, tiles 128x128, K%32==0.
// MODE 0: A plain. MODE 1: A rows = concat(memory, input_) virtual.
// EPI 0: fp32 C. EPI 1: half Ch. EPI 2: dual half: Ch=half(acc+Vb), C2h=half(acc+Ub).
// 128 threads = 4 warps 2(m)x2(n), warp 64x64; 4-stage cp.async ring,
// both tiles [row][k] pitch 40 halves (80B, conflict-free).
// ---------------------------------------------------------------------------
#define GEMMH_SMEM (4 * 20480)

template <int MODE, int EPI>
__global__ void __launch_bounds__(128) gemm_fp16(
    const __half* __restrict__ A, const __half* __restrict__ A2,
    const __half* __restrict__ Bt,
    float* __restrict__ C, __half* __restrict__ Ch, __half* __restrict__ C2h,
    const float* __restrict__ Vb, const float* __restrict__ Ub,
    int M, int N, int K)
{
    extern __shared__ __half smh[];
    const uint32_t sbase = smem_u32(smh);
    const int tid  = threadIdx.x;
    const int lane = tid & 31;
    const int w    = tid >> 5;
    const int wm   = (w >> 1) * 64;
    const int wn   = (w & 1) * 64;
    const int bm   = blockIdx.y * 128;
    const int bn   = blockIdx.x * 128;
    const int r    = lane >> 2;
    const int kb   = lane & 3;

    const __half* arow;
    if (MODE == 0) {
        arow = A + (size_t)(bm + tid) * K;
    } else {
        int row = bm + tid;
        int b   = row / TT;
        int rr  = row - b * TT;
        arow = (rr < PSQ) ? A  + (size_t)(b * PSQ + rr)         * K
                          : A2 + (size_t)(b * CSQ + (rr - PSQ)) * K;
    }
    const __half* brow = Bt + (size_t)(bn + tid) * K;

    auto issue = [&](int s, int k0) {
        uint32_t ab = sbase + s * 20480 + tid * 80;
        uint32_t bb = ab + 10240;
#pragma unroll
        for (int j = 0; j < 4; j++) {
            CPA16(ab + j * 16, arow + k0 + j * 8);
            CPA16(bb + j * 16, brow + k0 + j * 8);
        }
        CPA_COMMIT();
    };

    const int T = K / 32;
    issue(0, 0); issue(1, 32); issue(2, 64);

    float acc[4][8][4] = {};

    for (int t = 0; t < T; t++) {
        CPA_WAIT_TAIL(T - 1 - t);
        __syncthreads();
        if (t + 3 < T) issue((t + 3) & 3, (t + 3) * 32);
        const char* sb = (const char*)smh + (t & 3) * 20480;
#pragma unroll
        for (int kk = 0; kk < 32; kk += 16) {
            const int koff = kk * 2 + kb * 4;
            uint32_t a[4][4], b[8][2];
#pragma unroll
            for (int mt = 0; mt < 4; mt++) {
                const char* ab = sb + (wm + mt * 16 + r) * 80 + koff;
                a[mt][0] = *(const uint32_t*)(ab);
                a[mt][1] = *(const uint32_t*)(ab + 640);
                a[mt][2] = *(const uint32_t*)(ab + 16);
                a[mt][3] = *(const uint32_t*)(ab + 656);
            }
#pragma unroll
            for (int nt = 0; nt < 8; nt++) {
                const char* bb = sb + 10240 + (wn + nt * 8 + r) * 80 + koff;
                b[nt][0] = *(const uint32_t*)(bb);
                b[nt][1] = *(const uint32_t*)(bb + 16);
            }
#pragma unroll
            for (int mt = 0; mt < 4; mt++)
#pragma unroll
                for (int nt = 0; nt < 8; nt++)
                    mma16(acc[mt][nt], a[mt], b[nt]);
        }
    }

#pragma unroll
    for (int mt = 0; mt < 4; mt++) {
        int r0 = bm + wm + mt * 16 + r;
#pragma unroll
        for (int nt = 0; nt < 8; nt++) {
            int c0 = bn + wn + nt * 8 + kb * 2;
            if (EPI == 0) {
                *(float2*)&C[(size_t)r0 * N + c0]       = make_float2(acc[mt][nt][0], acc[mt][nt][1]);
                *(float2*)&C[(size_t)(r0 + 8) * N + c0] = make_float2(acc[mt][nt][2], acc[mt][nt][3]);
            } else if (EPI == 1) {
                *(__half2*)&Ch[(size_t)r0 * N + c0]       = __floats2half2_rn(acc[mt][nt][0], acc[mt][nt][1]);
                *(__half2*)&Ch[(size_t)(r0 + 8) * N + c0] = __floats2half2_rn(acc[mt][nt][2], acc[mt][nt][3]);
            } else {
                float v0 = Vb[c0], v1 = Vb[c0 + 1];
                float u0 = Ub[c0], u1 = Ub[c0 + 1];
                *(__half2*)&Ch[(size_t)r0 * N + c0]        = __floats2half2_rn(acc[mt][nt][0] + v0, acc[mt][nt][1] + v1);
                *(__half2*)&Ch[(size_t)(r0 + 8) * N + c0]  = __floats2half2_rn(acc[mt][nt][2] + v0, acc[mt][nt][3] + v1);
                *(__half2*)&C2h[(size_t)r0 * N + c0]       = __floats2half2_rn(acc[mt][nt][0] + u0, acc[mt][nt][1] + u1);
                *(__half2*)&C2h[(size_t)(r0 + 8) * N + c0] = __floats2half2_rn(acc[mt][nt][2] + u0, acc[mt][nt][3] + u1);
            }
        }
    }
}

// ---------------------------------------------------------------------------
// P[h][L][jj] = sum_d qv[L,h,d] * p[jj,h,d]   (NT, K=64, fp16 HMMA)
// Output HALF (halves the 512MB P stream). Single SMEM stage (whole K):
// both tiles [row][k=64] pitch 72 halves (conflict-free).
// ---------------------------------------------------------------------------
__global__ void __launch_bounds__(128) pos_gemm_fp16(
    const __half* __restrict__ qv, const __half* __restrict__ p,
    __half* __restrict__ P)
{
    __shared__ __half As[128][72];
    __shared__ __half Bs[128][72];
    const int tid  = threadIdx.x;
    const int lane = tid & 31;
    const int w    = tid >> 5;
    const int wm   = (w >> 1) * 64;
    const int wn   = (w & 1) * 64;
    const int h    = blockIdx.z;
    const int L0   = blockIdx.y * 128;
    const int j0   = blockIdx.x * 128;
    const int r    = lane >> 2;
    const int kb   = lane & 3;

    {
        const __half* ar = qv + (size_t)(L0 + tid) * HD + h * HDIM;
        const __half* br = p  + (size_t)(j0 + tid) * HD + h * HDIM;
        uint32_t ad = smem_u32(&As[tid][0]);
        uint32_t bd = smem_u32(&Bs[tid][0]);
#pragma unroll
        for (int j = 0; j < 8; j++) {
            CPA16(ad + j * 16, ar + j * 8);
            CPA16(bd + j * 16, br + j * 8);
        }
        CPA_COMMIT();
    }
    CPA_WAIT(0);
    __syncthreads();

    float acc[4][8][4] = {};
#pragma unroll
    for (int ks = 0; ks < 4; ks++) {
        const int koff = ks * 16 + kb * 2;
        uint32_t a[4][4], b[8][2];
#pragma unroll
        for (int mt = 0; mt < 4; mt++) {
            a[mt][0] = *(const uint32_t*)&As[wm + mt * 16 + r][koff];
            a[mt][1] = *(const uint32_t*)&As[wm + mt * 16 + r + 8][koff];
            a[mt][2] = *(const uint32_t*)&As[wm + mt * 16 + r][koff + 8];
            a[mt][3] = *(const uint32_t*)&As[wm + mt * 16 + r + 8][koff + 8];
        }
#pragma unroll
        for (int nt = 0; nt < 8; nt++) {
            b[nt][0] = *(const uint32_t*)&Bs[wn + nt * 8 + r][koff];
            b[nt][1] = *(const uint32_t*)&Bs[wn + nt * 8 + r][koff + 8];
        }
#pragma unroll
        for (int mt = 0; mt < 4; mt++)
#pragma unroll
            for (int nt = 0; nt < 8; nt++)
                mma16(acc[mt][nt], a[mt], b[nt]);
    }

#pragma unroll
    for (int mt = 0; mt < 4; mt++) {
        int r0 = L0 + wm + mt * 16 + r;
#pragma unroll
        for (int nt = 0; nt < 8; nt++) {
            int c0 = j0 + wn + nt * 8 + kb * 2;
            __half* o = P + ((size_t)h * LQG + r0) * TT + c0;
            *(__half2*)o            = __floats2half2_rn(acc[mt][nt][0], acc[mt][nt][1]);
            *(__half2*)(o + 8 * TT) = __floats2half2_rn(acc[mt][nt][2], acc[mt][nt][3]);
        }
    }
}

// ---------------------------------------------------------------------------
// rel_shift gather: pos(b,i,j) with L = b*CS+i  (half P)
// ---------------------------------------------------------------------------
__device__ __forceinline__ float pos_val(const __half* __restrict__ Pm,
                                         int h, int L, int jj)
{
    int s  = jj + LQG - L;
    int n  = (s > TT) + (s > 2 * TT + 1);
    int jp = s - n * (TT + 1);
    int Lp = L + n;
    float pos = 0.f;
    if (jp > 0 && Lp < LQG)
        pos = __half2float(Pm[((size_t)h * LQG + Lp) * TT + (jp - 1)]);
    return pos;
}

// ---------------------------------------------------------------------------
// Fused attention, fp16 MMA path (R13 structure; P now half).
// ---------------------------------------------------------------------------
#define ATT_SMEM ((128 * 72 + 64 * 72 + 64 * 72) * 2)

__global__ void __launch_bounds__(256) attn_fused_fp16(
    const __half* __restrict__ qu, const __half* __restrict__ kv,
    const __half* __restrict__ Pm, __half* __restrict__ ao)
{
    extern __shared__ __half dynh[];
    __half (*Sq)[72] = (__half(*)[72])dynh;                 // q staging, then probs
    __half (*Bk)[72] = (__half(*)[72])(dynh + 128 * 72);
    __half (*Bv)[72] = (__half(*)[72])(dynh + 128 * 72 + 64 * 72);

    const int tid  = threadIdx.x;
    const int lane = tid & 31;
    const int w    = tid >> 5;
    const int wm   = w * 16;
    const int bh   = blockIdx.y;
    const int b    = bh >> 4;
    const int h    = bh & 15;
    const int i0   = blockIdx.x * 128;
    const int r    = lane >> 2;
    const int kb   = lane & 3;

    // ---- stage qu rows, preload persistent A-fragments ----
    {
        int row = tid >> 1;
        int kq  = (tid & 1) * 32;
        const __half* qr = qu + (size_t)(b * CSQ + i0 + row) * HD + h * HDIM + kq;
#pragma unroll
        for (int i = 0; i < 4; i++)
            *(uint4*)&Sq[row][kq + i * 8] = *(const uint4*)(qr + i * 8);
    }
    __syncthreads();
    uint32_t aq[4][4];
#pragma unroll
    for (int ks = 0; ks < 4; ks++) {
        const int koff = ks * 16 + kb * 2;
        aq[ks][0] = *(const uint32_t*)&Sq[wm + r][koff];
        aq[ks][1] = *(const uint32_t*)&Sq[wm + r + 8][koff];
        aq[ks][2] = *(const uint32_t*)&Sq[wm + r][koff + 8];
        aq[ks][3] = *(const uint32_t*)&Sq[wm + r + 8][koff + 8];
    }
    __syncthreads();   // Sq region now free for probs

    float m0 = -3.0e38f, m1 = -3.0e38f, l0 = 0.f, l1 = 0.f;
    float acc_o[8][4] = {};

    const int row0 = i0 + wm + r;
    const int Lr   = b * CSQ + row0;
    const int Kef  = min(TT, i0 + 128 + PSQ);

    for (int j0 = 0; j0 < Kef; j0 += 64) {
        // ---- stage K (direct) and V (transposed) ----
        {
            int j  = tid & 63;
            int q4 = tid >> 6;   // 0..3, 16 halves each
            const __half* kr = kv + (size_t)(b * TT + j0 + j) * (2 * HD) + h * HDIM + q4 * 16;
            *(uint4*)&Bk[j][q4 * 16]     = *(const uint4*)(kr);
            *(uint4*)&Bk[j][q4 * 16 + 8] = *(const uint4*)(kr + 8);
            const __half* vr = kr + HD;
            uint4 v0 = *(const uint4*)(vr);
            uint4 v1 = *(const uint4*)(vr + 8);
            const __half* hv0 = (const __half*)&v0;
            const __half* hv1 = (const __half*)&v1;
#pragma unroll
            for (int i = 0; i < 8; i++) {
                Bv[q4 * 16 + i][j]     = hv0[i];
                Bv[q4 * 16 + 8 + i][j] = hv1[i];
            }
        }
        __syncthreads();

        // ---- score GEMM: warp computes 16 x 64 (fp16) ----
        float s[8][4] = {};
#pragma unroll
        for (int ks = 0; ks < 4; ks++) {
            const int koff = ks * 16 + kb * 2;
            uint32_t bq[8][2];
#pragma unroll
            for (int nt = 0; nt < 8; nt++) {
                bq[nt][0] = *(const uint32_t*)&Bk[nt * 8 + r][koff];
                bq[nt][1] = *(const uint32_t*)&Bk[nt * 8 + r][koff + 8];
            }
#pragma unroll
            for (int nt = 0; nt < 8; nt++)
                mma16(s[nt], aq[ks], bq[nt]);
        }

        // ---- epilogue: pos gather + mask + scale ----
#pragma unroll
        for (int nt = 0; nt < 8; nt++) {
            int jjb = j0 + nt * 8 + 2 * kb;
#pragma unroll
            for (int cc = 0; cc < 2; cc++) {
                int jj = jjb + cc;
                s[nt][cc]     = (jj > row0 + PSQ)     ? -1e30f
                              : (s[nt][cc]     + pos_val(Pm, h, Lr, jj))     * SCALE;
                s[nt][2 + cc] = (jj > row0 + 8 + PSQ) ? -1e30f
                              : (s[nt][2 + cc] + pos_val(Pm, h, Lr + 8, jj)) * SCALE;
            }
        }

        // ---- online softmax update (rows quad-local) ----
        float tm0 = -3.0e38f, tm1 = -3.0e38f;
#pragma unroll
        for (int nt = 0; nt < 8; nt++) {
            tm0 = fmaxf(tm0, fmaxf(s[nt][0], s[nt][1]));
            tm1 = fmaxf(tm1, fmaxf(s[nt][2], s[nt][3]));
        }
        tm0 = fmaxf(tm0, __shfl_xor_sync(0xffffffffu, tm0, 1));
        tm0 = fmaxf(tm0, __shfl_xor_sync(0xffffffffu, tm0, 2));
        tm1 = fmaxf(tm1, __shfl_xor_sync(0xffffffffu, tm1, 1));
        tm1 = fmaxf(tm1, __shfl_xor_sync(0xffffffffu, tm1, 2));
        float mn0 = fmaxf(m0, tm0), mn1 = fmaxf(m1, tm1);
        float f0 = __expf(m0 - mn0), f1 = __expf(m1 - mn1);

        float ps0 = 0.f, ps1 = 0.f;
#pragma unroll
        for (int nt = 0; nt < 8; nt++) {
            s[nt][0] = __expf(s[nt][0] - mn0);
            s[nt][1] = __expf(s[nt][1] - mn0);
            s[nt][2] = __expf(s[nt][2] - mn1);
            s[nt][3] = __expf(s[nt][3] - mn1);
            ps0 += s[nt][0] + s[nt][1];
            ps1 += s[nt][2] + s[nt][3];
        }
        ps0 += __shfl_xor_sync(0xffffffffu, ps0, 1);
        ps0 += __shfl_xor_sync(0xffffffffu, ps0, 2);
        ps1 += __shfl_xor_sync(0xffffffffu, ps1, 1);
        ps1 += __shfl_xor_sync(0xffffffffu, ps1, 2);
        l0 = l0 * f0 + ps0;
        l1 = l1 * f1 + ps1;
        m0 = mn0; m1 = mn1;

#pragma unroll
        for (int nt = 0; nt < 8; nt++) {
            acc_o[nt][0] *= f0; acc_o[nt][1] *= f0;
            acc_o[nt][2] *= f1; acc_o[nt][3] *= f1;
        }

        // ---- probs -> SMEM (half2 pairs, row-major [row][j], warp-private) ----
#pragma unroll
        for (int nt = 0; nt < 8; nt++) {
            int jl = nt * 8 + 2 * kb;
            *(__half2*)&Sq[wm + r][jl]     = __floats2half2_rn(s[nt][0], s[nt][1]);
            *(__half2*)&Sq[wm + r + 8][jl] = __floats2half2_rn(s[nt][2], s[nt][3]);
        }
        __syncwarp();

        // ---- O += probs @ V (fp16) ----
#pragma unroll
        for (int ks = 0; ks < 4; ks++) {
            const int koff = ks * 16 + kb * 2;
            uint32_t a[4];
            a[0] = *(const uint32_t*)&Sq[wm + r][koff];
            a[1] = *(const uint32_t*)&Sq[wm + r + 8][koff];
            a[2] = *(const uint32_t*)&Sq[wm + r][koff + 8];
            a[3] = *(const uint32_t*)&Sq[wm + r + 8][koff + 8];
            uint32_t bq[8][2];
#pragma unroll
            for (int nt = 0; nt < 8; nt++) {
                bq[nt][0] = *(const uint32_t*)&Bv[nt * 8 + r][koff];
                bq[nt][1] = *(const uint32_t*)&Bv[nt * 8 + r][koff + 8];
            }
#pragma unroll
            for (int nt = 0; nt < 8; nt++)
                mma16(acc_o[nt], a, bq[nt]);
        }
        __syncthreads();   // protect Bk/Bv/Sq before next tile
    }

    // ---- normalize and write ao (half) ----
    float inv0 = 1.0f / l0, inv1 = 1.0f / l1;
#pragma unroll
    for (int nt = 0; nt < 8; nt++) {
        int c0 = nt * 8 + 2 * kb;
        __half* o0 = ao + (size_t)(b * CSQ + row0) * HD + h * HDIM + c0;
        *(__half2*)o0            = __floats2half2_rn(acc_o[nt][0] * inv0, acc_o[nt][1] * inv0);
        *(__half2*)(o0 + 8 * HD) = __floats2half2_rn(acc_o[nt][2] * inv1, acc_o[nt][3] * inv1);
    }
}

// ---------------------------------------------------------------------------
// Launch. Inputs: input_, pos_embs, memory, u, v, W_kv, W_q, W_p, W_out, mask.
// ---------------------------------------------------------------------------
extern "C" void kernel_launch(void* const* d_in, const int* in_sizes, int n_in,
                              void* d_out, int out_size)
{
    const float* input_ = (const float*)d_in[0];
    const float* pos    = (const float*)d_in[1];
    const float* memory = (const float*)d_in[2];
    const float* u      = (const float*)d_in[3];
    const float* v      = (const float*)d_in[4];
    const float* W_kv   = (const float*)d_in[5];
    const float* W_q    = (const float*)d_in[6];
    const float* W_p    = (const float*)d_in[7];
    const float* W_out  = (const float*)d_in[8];
    float* out = (float*)d_out;

    __half *Pb, *qvh, *quh, *kvh, *ph, *aoh;
    __half *hin, *hmem, *hpos, *hWkv, *hWq, *hWp, *hWout;
    cudaGetSymbolAddress((void**)&Pb,   g_Ph);
    cudaGetSymbolAddress((void**)&qvh,  h_qv);
    cudaGetSymbolAddress((void**)&quh,  h_qu);
    cudaGetSymbolAddress((void**)&kvh,  h_kvh);
    cudaGetSymbolAddress((void**)&ph,   h_ph);
    cudaGetSymbolAddress((void**)&aoh,  h_aoh);
    cudaGetSymbolAddress((void**)&hin,  h_in);
    cudaGetSymbolAddress((void**)&hmem, h_mem);
    cudaGetSymbolAddress((void**)&hpos, h_pos);
    cudaGetSymbolAddress((void**)&hWkv, h_Wkv_t);
    cudaGetSymbolAddress((void**)&hWq,  h_Wq_t);
    cudaGetSymbolAddress((void**)&hWp,  h_Wp_t);
    cudaGetSymbolAddress((void**)&hWout, h_Wout_t);

    cudaFuncSetAttribute(gemm_fp16<0,0>, cudaFuncAttributeMaxDynamicSharedMemorySize, GEMMH_SMEM);
    cudaFuncSetAttribute(gemm_fp16<0,1>, cudaFuncAttributeMaxDynamicSharedMemorySize, GEMMH_SMEM);
    cudaFuncSetAttribute(gemm_fp16<0,2>, cudaFuncAttributeMaxDynamicSharedMemorySize, GEMMH_SMEM);
    cudaFuncSetAttribute(gemm_fp16<1,1>, cudaFuncAttributeMaxDynamicSharedMemorySize, GEMMH_SMEM);
    cudaFuncSetAttribute(attn_fused_fp16, cudaFuncAttributeMaxDynamicSharedMemorySize, ATT_SMEM);

    // ---- one-time conversions ----
    auto cvt = [&](const float* src, __half* dst, size_t n) {
        int n4 = (int)(n / 4);
        cvt_f2h<<<(n4 + 255) / 256, 256>>>(src, dst, n4);
    };
    cvt(input_, hin,  (size_t)BSZ * CSQ * DIN);
    cvt(memory, hmem, (size_t)BSZ * PSQ * DIN);
    cvt(pos,    hpos, (size_t)TT * DIN);
    transpose_f2h<<<dim3(HD / 32,     DIN / 32), 256>>>(W_q,   hWq,   DIN, HD);
    transpose_f2h<<<dim3(2 * HD / 32, DIN / 32), 256>>>(W_kv,  hWkv,  DIN, 2 * HD);
    transpose_f2h<<<dim3(HD / 32,     DIN / 32), 256>>>(W_p,   hWp,   DIN, HD);
    transpose_f2h<<<dim3(DIN / 32,    HD / 32),  256>>>(W_out, hWout, HD,  DIN);

    dim3 thr(128);

    // q-GEMM -> qv = half(q+v), qu = half(q+u)
    gemm_fp16<0,2><<<dim3(HD / 128, LQG / 128), thr, GEMMH_SMEM>>>(
        hin, nullptr, hWq, nullptr, qvh, quh, v, u, LQG, HD, DIN);
    // kv = concat(memory, input_) @ W_kv -> half
    gemm_fp16<1,1><<<dim3(2 * HD / 128, (BSZ * TT) / 128), thr, GEMMH_SMEM>>>(
        hmem, hin, hWkv, nullptr, kvh, nullptr, nullptr, nullptr, BSZ * TT, 2 * HD, DIN);
    // p = pos_embs @ W_p -> half
    gemm_fp16<0,1><<<dim3(HD / 128, TT / 128), thr, GEMMH_SMEM>>>(
        hpos, nullptr, hWp, nullptr, ph, nullptr, nullptr, nullptr, TT, HD, DIN);
    // P[h] = qv @ p^T per head (fp16 HMMA, half out)
    pos_gemm_fp16<<<dim3(TT / 128, LQG / 128, NH), thr>>>(qvh, ph, Pb);
    // fused attention (fp16 HMMA)
    attn_fused_fp16<<<dim3(CSQ / 128, BSZ * NH), 256, ATT_SMEM>>>(quh, kvh, Pb, aoh);
    // out = ao @ W_out (fp32 store)
    gemm_fp16<0,0><<<dim3(DIN / 128, LQG / 128), thr, GEMMH_SMEM>>>(
        aoh, nullptr, hWout, out, nullptr, nullptr, nullptr, nullptr, LQG, DIN, HD);
}

// round 15
// speedup vs baseline: 1.3141x; 1.3141x over previous
#include <cuda_runtime.h>
#include <cuda_fp16.h>
#include <cstdint>

// Problem constants
#define BSZ   4
#define CSQ   1024
#define PSQ   1024
#define DIN   1024
#define NH    16
#define HDIM  64
#define TT    2048        // T = CS + PS
#define LQG   4096        // BSZ*CSQ global query rows
#define HD    1024        // NH*HDIM
#define SCALE 0.125f      // 1/sqrt(64)

// ---------------------------------------------------------------------------
// Scratch (device globals; no dynamic allocation allowed)
// ---------------------------------------------------------------------------
__device__ float  g_P  [(size_t)NH * LQG * TT];          // 512 MB  pos scores (fp32)
__device__ __half h_qv [(size_t)LQG * HD];               //  8.4 MB half(q+v)
__device__ __half h_qu [(size_t)LQG * HD];               //  8.4 MB half(q+u)
__device__ __half h_kvh[(size_t)BSZ * TT * 2 * HD];      // 33.5 MB [k|v] half
__device__ __half h_ph [(size_t)TT * HD];                //  4.2 MB p half
__device__ __half h_aoh[(size_t)LQG * HD];               //  8.4 MB attn out half
// half inputs / transposed weights (one-time conversions)
__device__ __half h_in  [(size_t)BSZ * CSQ * DIN];
__device__ __half h_mem [(size_t)BSZ * PSQ * DIN];
__device__ __half h_pos [(size_t)TT * DIN];
__device__ __half h_Wkv_t [(size_t)(2 * HD) * DIN];      // [n][k]
__device__ __half h_Wq_t  [(size_t)HD * DIN];
__device__ __half h_Wp_t  [(size_t)HD * DIN];
__device__ __half h_Wout_t[(size_t)DIN * HD];

// ---------------------------------------------------------------------------
// Helpers
// ---------------------------------------------------------------------------
__device__ __forceinline__ void mma16(float* d, const uint32_t* a, const uint32_t* b) {
    asm volatile(
        "mma.sync.aligned.m16n8k16.row.col.f32.f16.f16.f32 "
        "{%0,%1,%2,%3}, {%4,%5,%6,%7}, {%8,%9}, {%0,%1,%2,%3};"
        : "+f"(d[0]), "+f"(d[1]), "+f"(d[2]), "+f"(d[3])
        : "r"(a[0]), "r"(a[1]), "r"(a[2]), "r"(a[3]), "r"(b[0]), "r"(b[1]));
}

__device__ __forceinline__ uint32_t smem_u32(const void* p) {
    return (uint32_t)__cvta_generic_to_shared(p);
}
#define CPA16(dst, src) \
    asm volatile("cp.async.cg.shared.global [%0], [%1], 16;" :: "r"(dst), "l"(src))
#define CPA_COMMIT() asm volatile("cp.async.commit_group;")
#define CPA_WAIT(n)  asm volatile("cp.async.wait_group %0;" :: "n"(n))
#define CPA_WAIT_TAIL(rem) do {                         \
        if ((rem) >= 2)      CPA_WAIT(2);               \
        else if ((rem) == 1) CPA_WAIT(1);               \
        else                 CPA_WAIT(0);               \
    } while (0)

// ---------------------------------------------------------------------------
// Merged one-time prep: elementwise f2h (input_, memory, pos_embs) and
// transposed f2h weights. One launch; block ranges select the job.
//   [0,4096)      input_ f2h        (4096 blocks of 256 float4)
//   [4096,8192)   memory f2h
//   [8192,10240)  pos f2h
//   [10240,11264) W_q   [DIN][HD]   -> [HD][DIN]
//   [11264,13312) W_kv  [DIN][2HD]  -> [2HD][DIN]
//   [13312,14336) W_p   [DIN][HD]   -> [HD][DIN]
//   [14336,15360) W_out [HD][DIN]   -> [DIN][HD]
// ---------------------------------------------------------------------------
#define PREP_BLOCKS 15360

__global__ void __launch_bounds__(256) prep_all(
    const float* __restrict__ in_, const float* __restrict__ mem_,
    const float* __restrict__ pos_,
    const float* __restrict__ Wq, const float* __restrict__ Wkv,
    const float* __restrict__ Wp, const float* __restrict__ Wout,
    __half* __restrict__ hin, __half* __restrict__ hmem, __half* __restrict__ hpos,
    __half* __restrict__ hWq, __half* __restrict__ hWkv,
    __half* __restrict__ hWp, __half* __restrict__ hWout)
{
    __shared__ __half tile[32][33];
    const int b = blockIdx.x;
    const int t = threadIdx.x;

    if (b < 10240) {
        const float* s; __half* d; int i;
        if (b < 4096)      { s = in_;  d = hin;  i = b * 256 + t; }
        else if (b < 8192) { s = mem_; d = hmem; i = (b - 4096) * 256 + t; }
        else               { s = pos_; d = hpos; i = (b - 8192) * 256 + t; }
        float4 v = ((const float4*)s)[i];
        __half2* o = (__half2*)d + (size_t)i * 2;
        o[0] = __floats2half2_rn(v.x, v.y);
        o[1] = __floats2half2_rn(v.z, v.w);
        return;
    }

    const float* src; __half* dst; int K, N, rb;
    if (b < 11264)      { src = Wq;   dst = hWq;   K = DIN; N = HD;     rb = b - 10240; }
    else if (b < 13312) { src = Wkv;  dst = hWkv;  K = DIN; N = 2 * HD; rb = b - 11264; }
    else if (b < 14336) { src = Wp;   dst = hWp;   K = DIN; N = HD;     rb = b - 13312; }
    else                { src = Wout; dst = hWout; K = HD;  N = DIN;    rb = b - 14336; }
    const int nx = N / 32;
    const int k0 = (rb / nx) * 32;
    const int n0 = (rb % nx) * 32;
    const int tx = t & 31, ty = t >> 5;
#pragma unroll
    for (int i = 0; i < 32; i += 8)
        tile[ty + i][tx] = __float2half(src[(size_t)(k0 + ty + i) * N + n0 + tx]);
    __syncthreads();
#pragma unroll
    for (int i = 0; i < 32; i += 8)
        dst[(size_t)(n0 + ty + i) * K + k0 + tx] = tile[tx][ty + i];
}

// ---------------------------------------------------------------------------
// fp16 NT GEMM: A(MxK half) @ Bt(NxK half)^T, tiles 128x128, K%32==0.
// MODE 0: A plain. MODE 1: A rows = concat(memory, input_) virtual.
// EPI 0: fp32 C. EPI 1: half Ch. EPI 2: dual half: Ch=half(acc+Vb), C2h=half(acc+Ub).
// 128 threads = 4 warps 2(m)x2(n), warp 64x64; 4-stage cp.async ring,
// both tiles [row][k] pitch 40 halves (80B, conflict-free).
// ---------------------------------------------------------------------------
#define GEMMH_SMEM (4 * 20480)

template <int MODE, int EPI>
__global__ void __launch_bounds__(128) gemm_fp16(
    const __half* __restrict__ A, const __half* __restrict__ A2,
    const __half* __restrict__ Bt,
    float* __restrict__ C, __half* __restrict__ Ch, __half* __restrict__ C2h,
    const float* __restrict__ Vb, const float* __restrict__ Ub,
    int M, int N, int K)
{
    extern __shared__ __half smh[];
    const uint32_t sbase = smem_u32(smh);
    const int tid  = threadIdx.x;
    const int lane = tid & 31;
    const int w    = tid >> 5;
    const int wm   = (w >> 1) * 64;
    const int wn   = (w & 1) * 64;
    const int bm   = blockIdx.y * 128;
    const int bn   = blockIdx.x * 128;
    const int r    = lane >> 2;
    const int kb   = lane & 3;

    const __half* arow;
    if (MODE == 0) {
        arow = A + (size_t)(bm + tid) * K;
    } else {
        int row = bm + tid;
        int b   = row / TT;
        int rr  = row - b * TT;
        arow = (rr < PSQ) ? A  + (size_t)(b * PSQ + rr)         * K
                          : A2 + (size_t)(b * CSQ + (rr - PSQ)) * K;
    }
    const __half* brow = Bt + (size_t)(bn + tid) * K;

    auto issue = [&](int s, int k0) {
        uint32_t ab = sbase + s * 20480 + tid * 80;
        uint32_t bb = ab + 10240;
#pragma unroll
        for (int j = 0; j < 4; j++) {
            CPA16(ab + j * 16, arow + k0 + j * 8);
            CPA16(bb + j * 16, brow + k0 + j * 8);
        }
        CPA_COMMIT();
    };

    const int T = K / 32;
    issue(0, 0); issue(1, 32); issue(2, 64);

    float acc[4][8][4] = {};

    for (int t = 0; t < T; t++) {
        CPA_WAIT_TAIL(T - 1 - t);
        __syncthreads();
        if (t + 3 < T) issue((t + 3) & 3, (t + 3) * 32);
        const char* sb = (const char*)smh + (t & 3) * 20480;
#pragma unroll
        for (int kk = 0; kk < 32; kk += 16) {
            const int koff = kk * 2 + kb * 4;
            uint32_t a[4][4], b[8][2];
#pragma unroll
            for (int mt = 0; mt < 4; mt++) {
                const char* ab = sb + (wm + mt * 16 + r) * 80 + koff;
                a[mt][0] = *(const uint32_t*)(ab);
                a[mt][1] = *(const uint32_t*)(ab + 640);
                a[mt][2] = *(const uint32_t*)(ab + 16);
                a[mt][3] = *(const uint32_t*)(ab + 656);
            }
#pragma unroll
            for (int nt = 0; nt < 8; nt++) {
                const char* bb = sb + 10240 + (wn + nt * 8 + r) * 80 + koff;
                b[nt][0] = *(const uint32_t*)(bb);
                b[nt][1] = *(const uint32_t*)(bb + 16);
            }
#pragma unroll
            for (int mt = 0; mt < 4; mt++)
#pragma unroll
                for (int nt = 0; nt < 8; nt++)
                    mma16(acc[mt][nt], a[mt], b[nt]);
        }
    }

#pragma unroll
    for (int mt = 0; mt < 4; mt++) {
        int r0 = bm + wm + mt * 16 + r;
#pragma unroll
        for (int nt = 0; nt < 8; nt++) {
            int c0 = bn + wn + nt * 8 + kb * 2;
            if (EPI == 0) {
                *(float2*)&C[(size_t)r0 * N + c0]       = make_float2(acc[mt][nt][0], acc[mt][nt][1]);
                *(float2*)&C[(size_t)(r0 + 8) * N + c0] = make_float2(acc[mt][nt][2], acc[mt][nt][3]);
            } else if (EPI == 1) {
                *(__half2*)&Ch[(size_t)r0 * N + c0]       = __floats2half2_rn(acc[mt][nt][0], acc[mt][nt][1]);
                *(__half2*)&Ch[(size_t)(r0 + 8) * N + c0] = __floats2half2_rn(acc[mt][nt][2], acc[mt][nt][3]);
            } else {
                float v0 = Vb[c0], v1 = Vb[c0 + 1];
                float u0 = Ub[c0], u1 = Ub[c0 + 1];
                *(__half2*)&Ch[(size_t)r0 * N + c0]        = __floats2half2_rn(acc[mt][nt][0] + v0, acc[mt][nt][1] + v1);
                *(__half2*)&Ch[(size_t)(r0 + 8) * N + c0]  = __floats2half2_rn(acc[mt][nt][2] + v0, acc[mt][nt][3] + v1);
                *(__half2*)&C2h[(size_t)r0 * N + c0]       = __floats2half2_rn(acc[mt][nt][0] + u0, acc[mt][nt][1] + u1);
                *(__half2*)&C2h[(size_t)(r0 + 8) * N + c0] = __floats2half2_rn(acc[mt][nt][2] + u0, acc[mt][nt][3] + u1);
            }
        }
    }
}

// ---------------------------------------------------------------------------
// P[h][L][jj] = sum_d qv[L,h,d] * p[jj,h,d]   (NT, K=64, fp16 HMMA, fp32 out)
// Single SMEM stage (whole K): both tiles [row][k=64] pitch 72 halves.
// ---------------------------------------------------------------------------
__global__ void __launch_bounds__(128) pos_gemm_fp16(
    const __half* __restrict__ qv, const __half* __restrict__ p,
    float* __restrict__ P)
{
    __shared__ __half As[128][72];
    __shared__ __half Bs[128][72];
    const int tid  = threadIdx.x;
    const int lane = tid & 31;
    const int w    = tid >> 5;
    const int wm   = (w >> 1) * 64;
    const int wn   = (w & 1) * 64;
    const int h    = blockIdx.z;
    const int L0   = blockIdx.y * 128;
    const int j0   = blockIdx.x * 128;
    const int r    = lane >> 2;
    const int kb   = lane & 3;

    {
        const __half* ar = qv + (size_t)(L0 + tid) * HD + h * HDIM;
        const __half* br = p  + (size_t)(j0 + tid) * HD + h * HDIM;
        uint32_t ad = smem_u32(&As[tid][0]);
        uint32_t bd = smem_u32(&Bs[tid][0]);
#pragma unroll
        for (int j = 0; j < 8; j++) {
            CPA16(ad + j * 16, ar + j * 8);
            CPA16(bd + j * 16, br + j * 8);
        }
        CPA_COMMIT();
    }
    CPA_WAIT(0);
    __syncthreads();

    float acc[4][8][4] = {};
#pragma unroll
    for (int ks = 0; ks < 4; ks++) {
        const int koff = ks * 16 + kb * 2;
        uint32_t a[4][4], b[8][2];
#pragma unroll
        for (int mt = 0; mt < 4; mt++) {
            a[mt][0] = *(const uint32_t*)&As[wm + mt * 16 + r][koff];
            a[mt][1] = *(const uint32_t*)&As[wm + mt * 16 + r + 8][koff];
            a[mt][2] = *(const uint32_t*)&As[wm + mt * 16 + r][koff + 8];
            a[mt][3] = *(const uint32_t*)&As[wm + mt * 16 + r + 8][koff + 8];
        }
#pragma unroll
        for (int nt = 0; nt < 8; nt++) {
            b[nt][0] = *(const uint32_t*)&Bs[wn + nt * 8 + r][koff];
            b[nt][1] = *(const uint32_t*)&Bs[wn + nt * 8 + r][koff + 8];
        }
#pragma unroll
        for (int mt = 0; mt < 4; mt++)
#pragma unroll
            for (int nt = 0; nt < 8; nt++)
                mma16(acc[mt][nt], a[mt], b[nt]);
    }

#pragma unroll
    for (int mt = 0; mt < 4; mt++) {
        int r0 = L0 + wm + mt * 16 + r;
#pragma unroll
        for (int nt = 0; nt < 8; nt++) {
            int c0 = j0 + wn + nt * 8 + kb * 2;
            float* o = P + ((size_t)h * LQG + r0) * TT + c0;
            *(float2*)o            = make_float2(acc[mt][nt][0], acc[mt][nt][1]);
            *(float2*)(o + 8 * TT) = make_float2(acc[mt][nt][2], acc[mt][nt][3]);
        }
    }
}

// ---------------------------------------------------------------------------
// rel_shift gather: pos(b,i,j) with L = b*CS+i  (fp32 P)
// ---------------------------------------------------------------------------
__device__ __forceinline__ float pos_val(const float* __restrict__ Pm,
                                         int h, int L, int jj)
{
    int s  = jj + LQG - L;
    int n  = (s > TT) + (s > 2 * TT + 1);
    int jp = s - n * (TT + 1);
    int Lp = L + n;
    float pos = 0.f;
    if (jp > 0 && Lp < LQG)
        pos = Pm[((size_t)h * LQG + Lp) * TT + (jp - 1)];
    return pos;
}

// ---------------------------------------------------------------------------
// Fused attention, fp16 MMA path. R13 structure MINUS the probs SMEM
// round-trip: for m16n8k16 the score C-fragment layout equals the PV
// A-fragment layout (a[0]=tile 2ks c0/c1, a[1]=c2/c3, a[2]=tile 2ks+1 c0/c1,
// a[3]=c2/c3), so probs convert register-to-register.
// SMEM (half): Sq 128*72 (q staging only) | Bk 64*72 | Bv 64*72.
// ---------------------------------------------------------------------------
#define ATT_SMEM ((128 * 72 + 64 * 72 + 64 * 72) * 2)

__global__ void __launch_bounds__(256) attn_fused_fp16(
    const __half* __restrict__ qu, const __half* __restrict__ kv,
    const float* __restrict__ Pm, __half* __restrict__ ao)
{
    extern __shared__ __half dynh[];
    __half (*Sq)[72] = (__half(*)[72])dynh;                 // q staging
    __half (*Bk)[72] = (__half(*)[72])(dynh + 128 * 72);
    __half (*Bv)[72] = (__half(*)[72])(dynh + 128 * 72 + 64 * 72);

    const int tid  = threadIdx.x;
    const int lane = tid & 31;
    const int w    = tid >> 5;
    const int wm   = w * 16;
    const int bh   = blockIdx.y;
    const int b    = bh >> 4;
    const int h    = bh & 15;
    const int i0   = blockIdx.x * 128;
    const int r    = lane >> 2;
    const int kb   = lane & 3;

    // ---- stage qu rows, preload persistent A-fragments ----
    {
        int row = tid >> 1;
        int kq  = (tid & 1) * 32;
        const __half* qr = qu + (size_t)(b * CSQ + i0 + row) * HD + h * HDIM + kq;
#pragma unroll
        for (int i = 0; i < 4; i++)
            *(uint4*)&Sq[row][kq + i * 8] = *(const uint4*)(qr + i * 8);
    }
    __syncthreads();
    uint32_t aq[4][4];
#pragma unroll
    for (int ks = 0; ks < 4; ks++) {
        const int koff = ks * 16 + kb * 2;
        aq[ks][0] = *(const uint32_t*)&Sq[wm + r][koff];
        aq[ks][1] = *(const uint32_t*)&Sq[wm + r + 8][koff];
        aq[ks][2] = *(const uint32_t*)&Sq[wm + r][koff + 8];
        aq[ks][3] = *(const uint32_t*)&Sq[wm + r + 8][koff + 8];
    }

    float m0 = -3.0e38f, m1 = -3.0e38f, l0 = 0.f, l1 = 0.f;
    float acc_o[8][4] = {};

    const int row0 = i0 + wm + r;
    const int Lr   = b * CSQ + row0;
    const int Kef  = min(TT, i0 + 128 + PSQ);

    for (int j0 = 0; j0 < Kef; j0 += 64) {
        // ---- stage K (direct) and V (transposed) ----
        {
            int j  = tid & 63;
            int q4 = tid >> 6;   // 0..3, 16 halves each
            const __half* kr = kv + (size_t)(b * TT + j0 + j) * (2 * HD) + h * HDIM + q4 * 16;
            *(uint4*)&Bk[j][q4 * 16]     = *(const uint4*)(kr);
            *(uint4*)&Bk[j][q4 * 16 + 8] = *(const uint4*)(kr + 8);
            const __half* vr = kr + HD;
            uint4 v0 = *(const uint4*)(vr);
            uint4 v1 = *(const uint4*)(vr + 8);
            const __half* hv0 = (const __half*)&v0;
            const __half* hv1 = (const __half*)&v1;
#pragma unroll
            for (int i = 0; i < 8; i++) {
                Bv[q4 * 16 + i][j]     = hv0[i];
                Bv[q4 * 16 + 8 + i][j] = hv1[i];
            }
        }
        __syncthreads();

        // ---- score GEMM: warp computes 16 x 64 (fp16) ----
        float s[8][4] = {};
#pragma unroll
        for (int ks = 0; ks < 4; ks++) {
            const int koff = ks * 16 + kb * 2;
            uint32_t bq[8][2];
#pragma unroll
            for (int nt = 0; nt < 8; nt++) {
                bq[nt][0] = *(const uint32_t*)&Bk[nt * 8 + r][koff];
                bq[nt][1] = *(const uint32_t*)&Bk[nt * 8 + r][koff + 8];
            }
#pragma unroll
            for (int nt = 0; nt < 8; nt++)
                mma16(s[nt], aq[ks], bq[nt]);
        }

        // ---- epilogue: pos gather + mask + scale ----
#pragma unroll
        for (int nt = 0; nt < 8; nt++) {
            int jjb = j0 + nt * 8 + 2 * kb;
#pragma unroll
            for (int cc = 0; cc < 2; cc++) {
                int jj = jjb + cc;
                s[nt][cc]     = (jj > row0 + PSQ)     ? -1e30f
                              : (s[nt][cc]     + pos_val(Pm, h, Lr, jj))     * SCALE;
                s[nt][2 + cc] = (jj > row0 + 8 + PSQ) ? -1e30f
                              : (s[nt][2 + cc] + pos_val(Pm, h, Lr + 8, jj)) * SCALE;
            }
        }

        // ---- online softmax update (rows quad-local) ----
        float tm0 = -3.0e38f, tm1 = -3.0e38f;
#pragma unroll
        for (int nt = 0; nt < 8; nt++) {
            tm0 = fmaxf(tm0, fmaxf(s[nt][0], s[nt][1]));
            tm1 = fmaxf(tm1, fmaxf(s[nt][2], s[nt][3]));
        }
        tm0 = fmaxf(tm0, __shfl_xor_sync(0xffffffffu, tm0, 1));
        tm0 = fmaxf(tm0, __shfl_xor_sync(0xffffffffu, tm0, 2));
        tm1 = fmaxf(tm1, __shfl_xor_sync(0xffffffffu, tm1, 1));
        tm1 = fmaxf(tm1, __shfl_xor_sync(0xffffffffu, tm1, 2));
        float mn0 = fmaxf(m0, tm0), mn1 = fmaxf(m1, tm1);
        float f0 = __expf(m0 - mn0), f1 = __expf(m1 - mn1);

        float ps0 = 0.f, ps1 = 0.f;
#pragma unroll
        for (int nt = 0; nt < 8; nt++) {
            s[nt][0] = __expf(s[nt][0] - mn0);
            s[nt][1] = __expf(s[nt][1] - mn0);
            s[nt][2] = __expf(s[nt][2] - mn1);
            s[nt][3] = __expf(s[nt][3] - mn1);
            ps0 += s[nt][0] + s[nt][1];
            ps1 += s[nt][2] + s[nt][3];
        }
        ps0 += __shfl_xor_sync(0xffffffffu, ps0, 1);
        ps0 += __shfl_xor_sync(0xffffffffu, ps0, 2);
        ps1 += __shfl_xor_sync(0xffffffffu, ps1, 1);
        ps1 += __shfl_xor_sync(0xffffffffu, ps1, 2);
        l0 = l0 * f0 + ps0;
        l1 = l1 * f1 + ps1;
        m0 = mn0; m1 = mn1;

#pragma unroll
        for (int nt = 0; nt < 8; nt++) {
            acc_o[nt][0] *= f0; acc_o[nt][1] *= f0;
            acc_o[nt][2] *= f1; acc_o[nt][3] *= f1;
        }

        // ---- O += probs @ V: probs fragments come straight from s regs ----
#pragma unroll
        for (int ks = 0; ks < 4; ks++) {
            const int koff = ks * 16 + kb * 2;
            uint32_t a[4];
            __half2 a0 = __floats2half2_rn(s[2 * ks][0],     s[2 * ks][1]);
            __half2 a1 = __floats2half2_rn(s[2 * ks][2],     s[2 * ks][3]);
            __half2 a2 = __floats2half2_rn(s[2 * ks + 1][0], s[2 * ks + 1][1]);
            __half2 a3 = __floats2half2_rn(s[2 * ks + 1][2], s[2 * ks + 1][3]);
            a[0] = *(const uint32_t*)&a0;
            a[1] = *(const uint32_t*)&a1;
            a[2] = *(const uint32_t*)&a2;
            a[3] = *(const uint32_t*)&a3;
            uint32_t bq[8][2];
#pragma unroll
            for (int nt = 0; nt < 8; nt++) {
                bq[nt][0] = *(const uint32_t*)&Bv[nt * 8 + r][koff];
                bq[nt][1] = *(const uint32_t*)&Bv[nt * 8 + r][koff + 8];
            }
#pragma unroll
            for (int nt = 0; nt < 8; nt++)
                mma16(acc_o[nt], a, bq[nt]);
        }
        __syncthreads();   // protect Bk/Bv before next tile
    }

    // ---- normalize and write ao (half) ----
    float inv0 = 1.0f / l0, inv1 = 1.0f / l1;
#pragma unroll
    for (int nt = 0; nt < 8; nt++) {
        int c0 = nt * 8 + 2 * kb;
        __half* o0 = ao + (size_t)(b * CSQ + row0) * HD + h * HDIM + c0;
        *(__half2*)o0            = __floats2half2_rn(acc_o[nt][0] * inv0, acc_o[nt][1] * inv0);
        *(__half2*)(o0 + 8 * HD) = __floats2half2_rn(acc_o[nt][2] * inv1, acc_o[nt][3] * inv1);
    }
}

// ---------------------------------------------------------------------------
// Launch. Inputs: input_, pos_embs, memory, u, v, W_kv, W_q, W_p, W_out, mask.
// Launch order: prep(1), q(2), kv(3), p(4), pos(5), attn(6), out(7) —
// ncu -s 5 -c 1 captures attn_fused_fp16.
// ---------------------------------------------------------------------------
extern "C" void kernel_launch(void* const* d_in, const int* in_sizes, int n_in,
                              void* d_out, int out_size)
{
    const float* input_ = (const float*)d_in[0];
    const float* pos    = (const float*)d_in[1];
    const float* memory = (const float*)d_in[2];
    const float* u      = (const float*)d_in[3];
    const float* v      = (const float*)d_in[4];
    const float* W_kv   = (const float*)d_in[5];
    const float* W_q    = (const float*)d_in[6];
    const float* W_p    = (const float*)d_in[7];
    const float* W_out  = (const float*)d_in[8];
    float* out = (float*)d_out;

    float *Pb;
    __half *qvh, *quh, *kvh, *ph, *aoh;
    __half *hin, *hmem, *hpos, *hWkv, *hWq, *hWp, *hWout;
    cudaGetSymbolAddress((void**)&Pb,   g_P);
    cudaGetSymbolAddress((void**)&qvh,  h_qv);
    cudaGetSymbolAddress((void**)&quh,  h_qu);
    cudaGetSymbolAddress((void**)&kvh,  h_kvh);
    cudaGetSymbolAddress((void**)&ph,   h_ph);
    cudaGetSymbolAddress((void**)&aoh,  h_aoh);
    cudaGetSymbolAddress((void**)&hin,  h_in);
    cudaGetSymbolAddress((void**)&hmem, h_mem);
    cudaGetSymbolAddress((void**)&hpos, h_pos);
    cudaGetSymbolAddress((void**)&hWkv, h_Wkv_t);
    cudaGetSymbolAddress((void**)&hWq,  h_Wq_t);
    cudaGetSymbolAddress((void**)&hWp,  h_Wp_t);
    cudaGetSymbolAddress((void**)&hWout, h_Wout_t);

    cudaFuncSetAttribute(gemm_fp16<0,0>, cudaFuncAttributeMaxDynamicSharedMemorySize, GEMMH_SMEM);
    cudaFuncSetAttribute(gemm_fp16<0,1>, cudaFuncAttributeMaxDynamicSharedMemorySize, GEMMH_SMEM);
    cudaFuncSetAttribute(gemm_fp16<0,2>, cudaFuncAttributeMaxDynamicSharedMemorySize, GEMMH_SMEM);
    cudaFuncSetAttribute(gemm_fp16<1,1>, cudaFuncAttributeMaxDynamicSharedMemorySize, GEMMH_SMEM);
    cudaFuncSetAttribute(attn_fused_fp16, cudaFuncAttributeMaxDynamicSharedMemorySize, ATT_SMEM);

    dim3 thr(128);

    // 1) merged one-time prep
    prep_all<<<PREP_BLOCKS, 256>>>(input_, memory, pos, W_q, W_kv, W_p, W_out,
                                   hin, hmem, hpos, hWq, hWkv, hWp, hWout);
    // 2) q-GEMM -> qv = half(q+v), qu = half(q+u)
    gemm_fp16<0,2><<<dim3(HD / 128, LQG / 128), thr, GEMMH_SMEM>>>(
        hin, nullptr, hWq, nullptr, qvh, quh, v, u, LQG, HD, DIN);
    // 3) kv = concat(memory, input_) @ W_kv -> half
    gemm_fp16<1,1><<<dim3(2 * HD / 128, (BSZ * TT) / 128), thr, GEMMH_SMEM>>>(
        hmem, hin, hWkv, nullptr, kvh, nullptr, nullptr, nullptr, BSZ * TT, 2 * HD, DIN);
    // 4) p = pos_embs @ W_p -> half
    gemm_fp16<0,1><<<dim3(HD / 128, TT / 128), thr, GEMMH_SMEM>>>(
        hpos, nullptr, hWp, nullptr, ph, nullptr, nullptr, nullptr, TT, HD, DIN);
    // 5) P[h] = qv @ p^T per head (fp16 HMMA, fp32 out)
    pos_gemm_fp16<<<dim3(TT / 128, LQG / 128, NH), thr>>>(qvh, ph, Pb);
    // 6) fused attention (fp16 HMMA)
    attn_fused_fp16<<<dim3(CSQ / 128, BSZ * NH), 256, ATT_SMEM>>>(quh, kvh, Pb, aoh);
    // 7) out = ao @ W_out (fp32 store)
    gemm_fp16<0,0><<<dim3(DIN / 128, LQG / 128), thr, GEMMH_SMEM>>>(
        aoh, nullptr, hWout, out, nullptr, nullptr, nullptr, nullptr, LQG, DIN, HD);
}

// round 16
// speedup vs baseline: 2.1209x; 1.6140x over previous
#include <cuda_runtime.h>
#include <cuda_fp16.h>
#include <cstdint>

// Problem constants
#define BSZ   4
#define CSQ   1024
#define PSQ   1024
#define DIN   1024
#define NH    16
#define HDIM  64
#define TT    2048        // T = CS + PS
#define LQG   4096        // BSZ*CSQ global query rows
#define HD    1024        // NH*HDIM
#define SCALE 0.125f      // 1/sqrt(64)

// ---------------------------------------------------------------------------
// Scratch (device globals; no dynamic allocation allowed)
// ---------------------------------------------------------------------------
__device__ float  g_P  [(size_t)NH * LQG * TT];          // 512 MB  pos scores (fp32)
__device__ __half h_qv [(size_t)LQG * HD];               //  8.4 MB half(q+v)
__device__ __half h_qu [(size_t)LQG * HD];               //  8.4 MB half(q+u)
__device__ __half h_kvh[(size_t)BSZ * TT * 2 * HD];      // 33.5 MB [k|v] half
__device__ __half h_ph [(size_t)TT * HD];                //  4.2 MB p half
__device__ __half h_aoh[(size_t)LQG * HD];               //  8.4 MB attn out half
// half inputs / transposed weights (one-time conversions)
__device__ __half h_in  [(size_t)BSZ * CSQ * DIN];
__device__ __half h_mem [(size_t)BSZ * PSQ * DIN];
__device__ __half h_pos [(size_t)TT * DIN];
__device__ __half h_Wkv_t [(size_t)(2 * HD) * DIN];      // [n][k]
__device__ __half h_Wq_t  [(size_t)HD * DIN];
__device__ __half h_Wp_t  [(size_t)HD * DIN];
__device__ __half h_Wout_t[(size_t)DIN * HD];

// ---------------------------------------------------------------------------
// Helpers
// ---------------------------------------------------------------------------
__device__ __forceinline__ void mma16(float* d, const uint32_t* a, const uint32_t* b) {
    asm volatile(
        "mma.sync.aligned.m16n8k16.row.col.f32.f16.f16.f32 "
        "{%0,%1,%2,%3}, {%4,%5,%6,%7}, {%8,%9}, {%0,%1,%2,%3};"
        : "+f"(d[0]), "+f"(d[1]), "+f"(d[2]), "+f"(d[3])
        : "r"(a[0]), "r"(a[1]), "r"(a[2]), "r"(a[3]), "r"(b[0]), "r"(b[1]));
}

__device__ __forceinline__ uint32_t smem_u32(const void* p) {
    return (uint32_t)__cvta_generic_to_shared(p);
}
#define CPA16(dst, src) \
    asm volatile("cp.async.cg.shared.global [%0], [%1], 16;" :: "r"(dst), "l"(src))
#define CPA_COMMIT() asm volatile("cp.async.commit_group;")
#define CPA_WAIT(n)  asm volatile("cp.async.wait_group %0;" :: "n"(n))
#define CPA_WAIT_TAIL(rem) do {                         \
        if ((rem) >= 2)      CPA_WAIT(2);               \
        else if ((rem) == 1) CPA_WAIT(1);               \
        else                 CPA_WAIT(0);               \
    } while (0)

// ---------------------------------------------------------------------------
// Merged one-time prep (unchanged from R15).
// ---------------------------------------------------------------------------
#define PREP_BLOCKS 15360

__global__ void __launch_bounds__(256) prep_all(
    const float* __restrict__ in_, const float* __restrict__ mem_,
    const float* __restrict__ pos_,
    const float* __restrict__ Wq, const float* __restrict__ Wkv,
    const float* __restrict__ Wp, const float* __restrict__ Wout,
    __half* __restrict__ hin, __half* __restrict__ hmem, __half* __restrict__ hpos,
    __half* __restrict__ hWq, __half* __restrict__ hWkv,
    __half* __restrict__ hWp, __half* __restrict__ hWout)
{
    __shared__ __half tile[32][33];
    const int b = blockIdx.x;
    const int t = threadIdx.x;

    if (b < 10240) {
        const float* s; __half* d; int i;
        if (b < 4096)      { s = in_;  d = hin;  i = b * 256 + t; }
        else if (b < 8192) { s = mem_; d = hmem; i = (b - 4096) * 256 + t; }
        else               { s = pos_; d = hpos; i = (b - 8192) * 256 + t; }
        float4 v = ((const float4*)s)[i];
        __half2* o = (__half2*)d + (size_t)i * 2;
        o[0] = __floats2half2_rn(v.x, v.y);
        o[1] = __floats2half2_rn(v.z, v.w);
        return;
    }

    const float* src; __half* dst; int K, N, rb;
    if (b < 11264)      { src = Wq;   dst = hWq;   K = DIN; N = HD;     rb = b - 10240; }
    else if (b < 13312) { src = Wkv;  dst = hWkv;  K = DIN; N = 2 * HD; rb = b - 11264; }
    else if (b < 14336) { src = Wp;   dst = hWp;   K = DIN; N = HD;     rb = b - 13312; }
    else                { src = Wout; dst = hWout; K = HD;  N = DIN;    rb = b - 14336; }
    const int nx = N / 32;
    const int k0 = (rb / nx) * 32;
    const int n0 = (rb % nx) * 32;
    const int tx = t & 31, ty = t >> 5;
#pragma unroll
    for (int i = 0; i < 32; i += 8)
        tile[ty + i][tx] = __float2half(src[(size_t)(k0 + ty + i) * N + n0 + tx]);
    __syncthreads();
#pragma unroll
    for (int i = 0; i < 32; i += 8)
        dst[(size_t)(n0 + ty + i) * K + k0 + tx] = tile[tx][ty + i];
}

// ---------------------------------------------------------------------------
// fp16 NT GEMM device body (same math/layout as R15 gemm_fp16).
// ---------------------------------------------------------------------------
#define GEMMH_SMEM (4 * 20480)

template <int MODE, int EPI>
__device__ __forceinline__ void gemm_dev(
    __half* smh, int bx, int by,
    const __half* __restrict__ A, const __half* __restrict__ A2,
    const __half* __restrict__ Bt,
    float* __restrict__ C, __half* __restrict__ Ch, __half* __restrict__ C2h,
    const float* __restrict__ Vb, const float* __restrict__ Ub,
    int M, int N, int K)
{
    const uint32_t sbase = smem_u32(smh);
    const int tid  = threadIdx.x;
    const int lane = tid & 31;
    const int w    = tid >> 5;
    const int wm   = (w >> 1) * 64;
    const int wn   = (w & 1) * 64;
    const int bm   = by * 128;
    const int bn   = bx * 128;
    const int r    = lane >> 2;
    const int kb   = lane & 3;

    const __half* arow;
    if (MODE == 0) {
        arow = A + (size_t)(bm + tid) * K;
    } else {
        int row = bm + tid;
        int b   = row / TT;
        int rr  = row - b * TT;
        arow = (rr < PSQ) ? A  + (size_t)(b * PSQ + rr)         * K
                          : A2 + (size_t)(b * CSQ + (rr - PSQ)) * K;
    }
    const __half* brow = Bt + (size_t)(bn + tid) * K;

    auto issue = [&](int s, int k0) {
        uint32_t ab = sbase + s * 20480 + tid * 80;
        uint32_t bb = ab + 10240;
#pragma unroll
        for (int j = 0; j < 4; j++) {
            CPA16(ab + j * 16, arow + k0 + j * 8);
            CPA16(bb + j * 16, brow + k0 + j * 8);
        }
        CPA_COMMIT();
    };

    const int T = K / 32;
    issue(0, 0); issue(1, 32); issue(2, 64);

    float acc[4][8][4] = {};

    for (int t = 0; t < T; t++) {
        CPA_WAIT_TAIL(T - 1 - t);
        __syncthreads();
        if (t + 3 < T) issue((t + 3) & 3, (t + 3) * 32);
        const char* sb = (const char*)smh + (t & 3) * 20480;
#pragma unroll
        for (int kk = 0; kk < 32; kk += 16) {
            const int koff = kk * 2 + kb * 4;
            uint32_t a[4][4], b[8][2];
#pragma unroll
            for (int mt = 0; mt < 4; mt++) {
                const char* ab = sb + (wm + mt * 16 + r) * 80 + koff;
                a[mt][0] = *(const uint32_t*)(ab);
                a[mt][1] = *(const uint32_t*)(ab + 640);
                a[mt][2] = *(const uint32_t*)(ab + 16);
                a[mt][3] = *(const uint32_t*)(ab + 656);
            }
#pragma unroll
            for (int nt = 0; nt < 8; nt++) {
                const char* bb = sb + 10240 + (wn + nt * 8 + r) * 80 + koff;
                b[nt][0] = *(const uint32_t*)(bb);
                b[nt][1] = *(const uint32_t*)(bb + 16);
            }
#pragma unroll
            for (int mt = 0; mt < 4; mt++)
#pragma unroll
                for (int nt = 0; nt < 8; nt++)
                    mma16(acc[mt][nt], a[mt], b[nt]);
        }
    }

#pragma unroll
    for (int mt = 0; mt < 4; mt++) {
        int r0 = bm + wm + mt * 16 + r;
#pragma unroll
        for (int nt = 0; nt < 8; nt++) {
            int c0 = bn + wn + nt * 8 + kb * 2;
            if (EPI == 0) {
                *(float2*)&C[(size_t)r0 * N + c0]       = make_float2(acc[mt][nt][0], acc[mt][nt][1]);
                *(float2*)&C[(size_t)(r0 + 8) * N + c0] = make_float2(acc[mt][nt][2], acc[mt][nt][3]);
            } else if (EPI == 1) {
                *(__half2*)&Ch[(size_t)r0 * N + c0]       = __floats2half2_rn(acc[mt][nt][0], acc[mt][nt][1]);
                *(__half2*)&Ch[(size_t)(r0 + 8) * N + c0] = __floats2half2_rn(acc[mt][nt][2], acc[mt][nt][3]);
            } else {
                float v0 = Vb[c0], v1 = Vb[c0 + 1];
                float u0 = Ub[c0], u1 = Ub[c0 + 1];
                *(__half2*)&Ch[(size_t)r0 * N + c0]        = __floats2half2_rn(acc[mt][nt][0] + v0, acc[mt][nt][1] + v1);
                *(__half2*)&Ch[(size_t)(r0 + 8) * N + c0]  = __floats2half2_rn(acc[mt][nt][2] + v0, acc[mt][nt][3] + v1);
                *(__half2*)&C2h[(size_t)r0 * N + c0]       = __floats2half2_rn(acc[mt][nt][0] + u0, acc[mt][nt][1] + u1);
                *(__half2*)&C2h[(size_t)(r0 + 8) * N + c0] = __floats2half2_rn(acc[mt][nt][2] + u0, acc[mt][nt][3] + u1);
            }
        }
    }
}

// Standalone GEMM kernel (used for out-GEMM)
template <int MODE, int EPI>
__global__ void __launch_bounds__(128) gemm_fp16(
    const __half* __restrict__ A, const __half* __restrict__ A2,
    const __half* __restrict__ Bt,
    float* __restrict__ C, __half* __restrict__ Ch, __half* __restrict__ C2h,
    const float* __restrict__ Vb, const float* __restrict__ Ub,
    int M, int N, int K)
{
    extern __shared__ __half smh[];
    gemm_dev<MODE, EPI>(smh, blockIdx.x, blockIdx.y, A, A2, Bt, C, Ch, C2h,
                        Vb, Ub, M, N, K);
}

// Merged q/kv/p projections: one launch fills the chip.
//   blocks [0,256):     q    8 n-tiles x 32 m-tiles  (EPI 2: qv/qu dual out)
//   blocks [256,1280):  kv  16 n-tiles x 64 m-tiles  (MODE 1, EPI 1)
//   blocks [1280,1408): p    8 n-tiles x 16 m-tiles  (EPI 1)
#define PROJ_BLOCKS 1408

__global__ void __launch_bounds__(128) proj_all(
    const __half* __restrict__ hin, const __half* __restrict__ hmem,
    const __half* __restrict__ hpos,
    const __half* __restrict__ hWq, const __half* __restrict__ hWkv,
    const __half* __restrict__ hWp,
    __half* __restrict__ qvh, __half* __restrict__ quh,
    __half* __restrict__ kvh, __half* __restrict__ ph,
    const float* __restrict__ v, const float* __restrict__ u)
{
    extern __shared__ __half smh[];
    const int b = blockIdx.x;
    if (b < 256) {
        gemm_dev<0, 2>(smh, b & 7, b >> 3, hin, nullptr, hWq,
                       nullptr, qvh, quh, v, u, LQG, HD, DIN);
    } else if (b < 1280) {
        int bb = b - 256;
        gemm_dev<1, 1>(smh, bb & 15, bb >> 4, hmem, hin, hWkv,
                       nullptr, kvh, nullptr, nullptr, nullptr, BSZ * TT, 2 * HD, DIN);
    } else {
        int bb = b - 1280;
        gemm_dev<0, 1>(smh, bb & 7, bb >> 3, hpos, nullptr, hWp,
                       nullptr, ph, nullptr, nullptr, nullptr, TT, HD, DIN);
    }
}

// ---------------------------------------------------------------------------
// P[h][L][jj] = sum_d qv[L,h,d] * p[jj,h,d]   (NT, K=64, fp16 HMMA, fp32 out)
// (Unchanged from R15.)
// ---------------------------------------------------------------------------
__global__ void __launch_bounds__(128) pos_gemm_fp16(
    const __half* __restrict__ qv, const __half* __restrict__ p,
    float* __restrict__ P)
{
    __shared__ __half As[128][72];
    __shared__ __half Bs[128][72];
    const int tid  = threadIdx.x;
    const int lane = tid & 31;
    const int w    = tid >> 5;
    const int wm   = (w >> 1) * 64;
    const int wn   = (w & 1) * 64;
    const int h    = blockIdx.z;
    const int L0   = blockIdx.y * 128;
    const int j0   = blockIdx.x * 128;
    const int r    = lane >> 2;
    const int kb   = lane & 3;

    {
        const __half* ar = qv + (size_t)(L0 + tid) * HD + h * HDIM;
        const __half* br = p  + (size_t)(j0 + tid) * HD + h * HDIM;
        uint32_t ad = smem_u32(&As[tid][0]);
        uint32_t bd = smem_u32(&Bs[tid][0]);
#pragma unroll
        for (int j = 0; j < 8; j++) {
            CPA16(ad + j * 16, ar + j * 8);
            CPA16(bd + j * 16, br + j * 8);
        }
        CPA_COMMIT();
    }
    CPA_WAIT(0);
    __syncthreads();

    float acc[4][8][4] = {};
#pragma unroll
    for (int ks = 0; ks < 4; ks++) {
        const int koff = ks * 16 + kb * 2;
        uint32_t a[4][4], b[8][2];
#pragma unroll
        for (int mt = 0; mt < 4; mt++) {
            a[mt][0] = *(const uint32_t*)&As[wm + mt * 16 + r][koff];
            a[mt][1] = *(const uint32_t*)&As[wm + mt * 16 + r + 8][koff];
            a[mt][2] = *(const uint32_t*)&As[wm + mt * 16 + r][koff + 8];
            a[mt][3] = *(const uint32_t*)&As[wm + mt * 16 + r + 8][koff + 8];
        }
#pragma unroll
        for (int nt = 0; nt < 8; nt++) {
            b[nt][0] = *(const uint32_t*)&Bs[wn + nt * 8 + r][koff];
            b[nt][1] = *(const uint32_t*)&Bs[wn + nt * 8 + r][koff + 8];
        }
#pragma unroll
        for (int mt = 0; mt < 4; mt++)
#pragma unroll
            for (int nt = 0; nt < 8; nt++)
                mma16(acc[mt][nt], a[mt], b[nt]);
    }

#pragma unroll
    for (int mt = 0; mt < 4; mt++) {
        int r0 = L0 + wm + mt * 16 + r;
#pragma unroll
        for (int nt = 0; nt < 8; nt++) {
            int c0 = j0 + wn + nt * 8 + kb * 2;
            float* o = P + ((size_t)h * LQG + r0) * TT + c0;
            *(float2*)o            = make_float2(acc[mt][nt][0], acc[mt][nt][1]);
            *(float2*)(o + 8 * TT) = make_float2(acc[mt][nt][2], acc[mt][nt][3]);
        }
    }
}

// ---------------------------------------------------------------------------
// rel_shift gather: pos(b,i,j) with L = b*CS+i  (fp32 P)
// ---------------------------------------------------------------------------
__device__ __forceinline__ float pos_val(const float* __restrict__ Pm,
                                         int h, int L, int jj)
{
    int s  = jj + LQG - L;
    int n  = (s > TT) + (s > 2 * TT + 1);
    int jp = s - n * (TT + 1);
    int Lp = L + n;
    float pos = 0.f;
    if (jp > 0 && Lp < LQG)
        pos = Pm[((size_t)h * LQG + Lp) * TT + (jp - 1)];
    return pos;
}

// ---------------------------------------------------------------------------
// Fused attention, fp16 MMA path. R15 structure plus:
//  * pos gather prefetched BEFORE the score MMA (hides DRAM latency)
//  * next K/V tile register-prefetched during compute, STS after the sync
// ---------------------------------------------------------------------------
#define ATT_SMEM ((128 * 72 + 64 * 72 + 64 * 72) * 2)

__global__ void __launch_bounds__(256) attn_fused_fp16(
    const __half* __restrict__ qu, const __half* __restrict__ kv,
    const float* __restrict__ Pm, __half* __restrict__ ao)
{
    extern __shared__ __half dynh[];
    __half (*Sq)[72] = (__half(*)[72])dynh;                 // q staging
    __half (*Bk)[72] = (__half(*)[72])(dynh + 128 * 72);
    __half (*Bv)[72] = (__half(*)[72])(dynh + 128 * 72 + 64 * 72);

    const int tid  = threadIdx.x;
    const int lane = tid & 31;
    const int w    = tid >> 5;
    const int wm   = w * 16;
    const int bh   = blockIdx.y;
    const int b    = bh >> 4;
    const int h    = bh & 15;
    const int i0   = blockIdx.x * 128;
    const int r    = lane >> 2;
    const int kb   = lane & 3;

    // ---- stage qu rows, preload persistent A-fragments ----
    {
        int row = tid >> 1;
        int kq  = (tid & 1) * 32;
        const __half* qr = qu + (size_t)(b * CSQ + i0 + row) * HD + h * HDIM + kq;
#pragma unroll
        for (int i = 0; i < 4; i++)
            *(uint4*)&Sq[row][kq + i * 8] = *(const uint4*)(qr + i * 8);
    }
    __syncthreads();
    uint32_t aq[4][4];
#pragma unroll
    for (int ks = 0; ks < 4; ks++) {
        const int koff = ks * 16 + kb * 2;
        aq[ks][0] = *(const uint32_t*)&Sq[wm + r][koff];
        aq[ks][1] = *(const uint32_t*)&Sq[wm + r + 8][koff];
        aq[ks][2] = *(const uint32_t*)&Sq[wm + r][koff + 8];
        aq[ks][3] = *(const uint32_t*)&Sq[wm + r + 8][koff + 8];
    }

    float m0 = -3.0e38f, m1 = -3.0e38f, l0 = 0.f, l1 = 0.f;
    float acc_o[8][4] = {};

    const int row0 = i0 + wm + r;
    const int Lr   = b * CSQ + row0;
    const int Kef  = min(TT, i0 + 128 + PSQ);

    // K/V staging lanes
    const int sj  = tid & 63;
    const int sq4 = tid >> 6;     // 0..3, 16 halves each

    // staging registers
    uint4 rk0, rk1, rv0, rv1;
    auto load_regs = [&](int j0) {
        const __half* kr = kv + (size_t)(b * TT + j0 + sj) * (2 * HD) + h * HDIM + sq4 * 16;
        rk0 = *(const uint4*)(kr);
        rk1 = *(const uint4*)(kr + 8);
        const __half* vr = kr + HD;
        rv0 = *(const uint4*)(vr);
        rv1 = *(const uint4*)(vr + 8);
    };
    auto store_smem = [&]() {
        *(uint4*)&Bk[sj][sq4 * 16]     = rk0;
        *(uint4*)&Bk[sj][sq4 * 16 + 8] = rk1;
        const __half* hv0 = (const __half*)&rv0;
        const __half* hv1 = (const __half*)&rv1;
#pragma unroll
        for (int i = 0; i < 8; i++) {
            Bv[sq4 * 16 + i][sj]     = hv0[i];
            Bv[sq4 * 16 + 8 + i][sj] = hv1[i];
        }
    };

    load_regs(0);
    store_smem();
    __syncthreads();

    for (int j0 = 0; j0 < Kef; j0 += 64) {
        const bool more = (j0 + 64 < Kef);
        if (more) load_regs(j0 + 64);      // next K/V tile in flight

        // ---- pos gather prefetch (independent of the MMAs below) ----
        float posv[8][4];
#pragma unroll
        for (int nt = 0; nt < 8; nt++) {
            int jjb = j0 + nt * 8 + 2 * kb;
            posv[nt][0] = pos_val(Pm, h, Lr, jjb);
            posv[nt][1] = pos_val(Pm, h, Lr, jjb + 1);
            posv[nt][2] = pos_val(Pm, h, Lr + 8, jjb);
            posv[nt][3] = pos_val(Pm, h, Lr + 8, jjb + 1);
        }

        // ---- score GEMM: warp computes 16 x 64 (fp16) ----
        float s[8][4] = {};
#pragma unroll
        for (int ks = 0; ks < 4; ks++) {
            const int koff = ks * 16 + kb * 2;
            uint32_t bq[8][2];
#pragma unroll
            for (int nt = 0; nt < 8; nt++) {
                bq[nt][0] = *(const uint32_t*)&Bk[nt * 8 + r][koff];
                bq[nt][1] = *(const uint32_t*)&Bk[nt * 8 + r][koff + 8];
            }
#pragma unroll
            for (int nt = 0; nt < 8; nt++)
                mma16(s[nt], aq[ks], bq[nt]);
        }

        // ---- epilogue: pos add + mask + scale ----
#pragma unroll
        for (int nt = 0; nt < 8; nt++) {
            int jjb = j0 + nt * 8 + 2 * kb;
#pragma unroll
            for (int cc = 0; cc < 2; cc++) {
                int jj = jjb + cc;
                s[nt][cc]     = (jj > row0 + PSQ)     ? -1e30f
                              : (s[nt][cc]     + posv[nt][cc])     * SCALE;
                s[nt][2 + cc] = (jj > row0 + 8 + PSQ) ? -1e30f
                              : (s[nt][2 + cc] + posv[nt][2 + cc]) * SCALE;
            }
        }

        // ---- online softmax update (rows quad-local) ----
        float tm0 = -3.0e38f, tm1 = -3.0e38f;
#pragma unroll
        for (int nt = 0; nt < 8; nt++) {
            tm0 = fmaxf(tm0, fmaxf(s[nt][0], s[nt][1]));
            tm1 = fmaxf(tm1, fmaxf(s[nt][2], s[nt][3]));
        }
        tm0 = fmaxf(tm0, __shfl_xor_sync(0xffffffffu, tm0, 1));
        tm0 = fmaxf(tm0, __shfl_xor_sync(0xffffffffu, tm0, 2));
        tm1 = fmaxf(tm1, __shfl_xor_sync(0xffffffffu, tm1, 1));
        tm1 = fmaxf(tm1, __shfl_xor_sync(0xffffffffu, tm1, 2));
        float mn0 = fmaxf(m0, tm0), mn1 = fmaxf(m1, tm1);
        float f0 = __expf(m0 - mn0), f1 = __expf(m1 - mn1);

        float ps0 = 0.f, ps1 = 0.f;
#pragma unroll
        for (int nt = 0; nt < 8; nt++) {
            s[nt][0] = __expf(s[nt][0] - mn0);
            s[nt][1] = __expf(s[nt][1] - mn0);
            s[nt][2] = __expf(s[nt][2] - mn1);
            s[nt][3] = __expf(s[nt][3] - mn1);
            ps0 += s[nt][0] + s[nt][1];
            ps1 += s[nt][2] + s[nt][3];
        }
        ps0 += __shfl_xor_sync(0xffffffffu, ps0, 1);
        ps0 += __shfl_xor_sync(0xffffffffu, ps0, 2);
        ps1 += __shfl_xor_sync(0xffffffffu, ps1, 1);
        ps1 += __shfl_xor_sync(0xffffffffu, ps1, 2);
        l0 = l0 * f0 + ps0;
        l1 = l1 * f1 + ps1;
        m0 = mn0; m1 = mn1;

#pragma unroll
        for (int nt = 0; nt < 8; nt++) {
            acc_o[nt][0] *= f0; acc_o[nt][1] *= f0;
            acc_o[nt][2] *= f1; acc_o[nt][3] *= f1;
        }

        // ---- O += probs @ V: probs fragments straight from s regs ----
#pragma unroll
        for (int ks = 0; ks < 4; ks++) {
            const int koff = ks * 16 + kb * 2;
            uint32_t a[4];
            __half2 a0 = __floats2half2_rn(s[2 * ks][0],     s[2 * ks][1]);
            __half2 a1 = __floats2half2_rn(s[2 * ks][2],     s[2 * ks][3]);
            __half2 a2 = __floats2half2_rn(s[2 * ks + 1][0], s[2 * ks + 1][1]);
            __half2 a3 = __floats2half2_rn(s[2 * ks + 1][2], s[2 * ks + 1][3]);
            a[0] = *(const uint32_t*)&a0;
            a[1] = *(const uint32_t*)&a1;
            a[2] = *(const uint32_t*)&a2;
            a[3] = *(const uint32_t*)&a3;
            uint32_t bq[8][2];
#pragma unroll
            for (int nt = 0; nt < 8; nt++) {
                bq[nt][0] = *(const uint32_t*)&Bv[nt * 8 + r][koff];
                bq[nt][1] = *(const uint32_t*)&Bv[nt * 8 + r][koff + 8];
            }
#pragma unroll
            for (int nt = 0; nt < 8; nt++)
                mma16(acc_o[nt], a, bq[nt]);
        }
        __syncthreads();                    // all warps done with Bk/Bv
        if (more) { store_smem(); __syncthreads(); }
    }

    // ---- normalize and write ao (half) ----
    float inv0 = 1.0f / l0, inv1 = 1.0f / l1;
#pragma unroll
    for (int nt = 0; nt < 8; nt++) {
        int c0 = nt * 8 + 2 * kb;
        __half* o0 = ao + (size_t)(b * CSQ + row0) * HD + h * HDIM + c0;
        *(__half2*)o0            = __floats2half2_rn(acc_o[nt][0] * inv0, acc_o[nt][1] * inv0);
        *(__half2*)(o0 + 8 * HD) = __floats2half2_rn(acc_o[nt][2] * inv1, acc_o[nt][3] * inv1);
    }
}

// ---------------------------------------------------------------------------
// Launch. Inputs: input_, pos_embs, memory, u, v, W_kv, W_q, W_p, W_out, mask.
// Order: prep(1), proj_all(2), pos(3), attn(4), out(5).
// ---------------------------------------------------------------------------
extern "C" void kernel_launch(void* const* d_in, const int* in_sizes, int n_in,
                              void* d_out, int out_size)
{
    const float* input_ = (const float*)d_in[0];
    const float* pos    = (const float*)d_in[1];
    const float* memory = (const float*)d_in[2];
    const float* u      = (const float*)d_in[3];
    const float* v      = (const float*)d_in[4];
    const float* W_kv   = (const float*)d_in[5];
    const float* W_q    = (const float*)d_in[6];
    const float* W_p    = (const float*)d_in[7];
    const float* W_out  = (const float*)d_in[8];
    float* out = (float*)d_out;

    float *Pb;
    __half *qvh, *quh, *kvh, *ph, *aoh;
    __half *hin, *hmem, *hpos, *hWkv, *hWq, *hWp, *hWout;
    cudaGetSymbolAddress((void**)&Pb,   g_P);
    cudaGetSymbolAddress((void**)&qvh,  h_qv);
    cudaGetSymbolAddress((void**)&quh,  h_qu);
    cudaGetSymbolAddress((void**)&kvh,  h_kvh);
    cudaGetSymbolAddress((void**)&ph,   h_ph);
    cudaGetSymbolAddress((void**)&aoh,  h_aoh);
    cudaGetSymbolAddress((void**)&hin,  h_in);
    cudaGetSymbolAddress((void**)&hmem, h_mem);
    cudaGetSymbolAddress((void**)&hpos, h_pos);
    cudaGetSymbolAddress((void**)&hWkv, h_Wkv_t);
    cudaGetSymbolAddress((void**)&hWq,  h_Wq_t);
    cudaGetSymbolAddress((void**)&hWp,  h_Wp_t);
    cudaGetSymbolAddress((void**)&hWout, h_Wout_t);

    cudaFuncSetAttribute(proj_all,       cudaFuncAttributeMaxDynamicSharedMemorySize, GEMMH_SMEM);
    cudaFuncSetAttribute(gemm_fp16<0,0>, cudaFuncAttributeMaxDynamicSharedMemorySize, GEMMH_SMEM);
    cudaFuncSetAttribute(attn_fused_fp16, cudaFuncAttributeMaxDynamicSharedMemorySize, ATT_SMEM);

    // 1) merged one-time prep
    prep_all<<<PREP_BLOCKS, 256>>>(input_, memory, pos, W_q, W_kv, W_p, W_out,
                                   hin, hmem, hpos, hWq, hWkv, hWp, hWout);
    // 2) merged q/kv/p projections (fills the chip)
    proj_all<<<PROJ_BLOCKS, 128, GEMMH_SMEM>>>(hin, hmem, hpos, hWq, hWkv, hWp,
                                               qvh, quh, kvh, ph, v, u);
    // 3) P[h] = qv @ p^T per head (fp16 HMMA, fp32 out)
    pos_gemm_fp16<<<dim3(TT / 128, LQG / 128, NH), 128>>>(qvh, ph, Pb);
    // 4) fused attention (fp16 HMMA)
    attn_fused_fp16<<<dim3(CSQ / 128, BSZ * NH), 256, ATT_SMEM>>>(quh, kvh, Pb, aoh);
    // 5) out = ao @ W_out (fp32 store)
    gemm_fp16<0,0><<<dim3(DIN / 128, LQG / 128), 128, GEMMH_SMEM>>>(
        aoh, nullptr, hWout, out, nullptr, nullptr, nullptr, nullptr, LQG, DIN, HD);
}